// round 9
// baseline (speedup 1.0000x reference)
#include <cuda_runtime.h>
#include <cuda_fp16.h>
#include <math.h>
#include <stdint.h>

// Problem constants
#define Bsz 2
#define Tq  2048
#define Cdim 1024
#define Hh  16
#define Dd  64
#define Mrows (Bsz*Tq)   // 4096

// ---------------------------------------------------------------------------
// Device-global scratch (sanctioned no-alloc path)
// ---------------------------------------------------------------------------
__device__ __align__(16) __half g_xh[Mrows*Cdim];
__device__ __align__(16) __half g_Wh[4*Cdim*Cdim];   // Wq,Wk,Wv,Wp packed
__device__ __align__(16) __half g_Qh[Mrows*Cdim];
__device__ __align__(16) __half g_Kh[Mrows*Cdim];
__device__ __align__(16) __half g_Vh[Mrows*Cdim];
__device__ __align__(16) __half g_Oh[Mrows*Cdim];

// ---------------------------------------------------------------------------
// Helpers (family-portable ISA)
// ---------------------------------------------------------------------------
__device__ __forceinline__ uint32_t smem_u32(const void* p) {
    uint32_t a;
    asm("{ .reg .u64 t; cvta.to.shared.u64 t, %1; cvt.u32.u64 %0, t; }"
        : "=r"(a) : "l"(p));
    return a;
}
__device__ __forceinline__ void cp16(uint32_t dst, const void* src) {
    asm volatile("cp.async.cg.shared.global [%0], [%1], 16;"
                 :: "r"(dst), "l"(src));
}
__device__ __forceinline__ void cp_commit() {
    asm volatile("cp.async.commit_group;");
}
template<int N> __device__ __forceinline__ void cp_wait() {
    asm volatile("cp.async.wait_group %0;" :: "n"(N));
}
__device__ __forceinline__ void mma_h(
    float& c0, float& c1, float& c2, float& c3,
    uint32_t a0, uint32_t a1, uint32_t a2, uint32_t a3,
    uint32_t b0, uint32_t b1)
{
    asm volatile(
        "mma.sync.aligned.m16n8k16.row.col.f32.f16.f16.f32 "
        "{%0,%1,%2,%3}, {%4,%5,%6,%7}, {%8,%9}, {%0,%1,%2,%3};"
        : "+f"(c0), "+f"(c1), "+f"(c2), "+f"(c3)
        : "r"(a0), "r"(a1), "r"(a2), "r"(a3), "r"(b0), "r"(b1));
}
__device__ __forceinline__ void ldsm4(
    uint32_t& r0, uint32_t& r1, uint32_t& r2, uint32_t& r3, uint32_t addr)
{
    asm volatile("ldmatrix.sync.aligned.m8n8.x4.shared.b16 {%0,%1,%2,%3}, [%4];"
        : "=r"(r0), "=r"(r1), "=r"(r2), "=r"(r3) : "r"(addr));
}
__device__ __forceinline__ void ldsm4t(
    uint32_t& r0, uint32_t& r1, uint32_t& r2, uint32_t& r3, uint32_t addr)
{
    asm volatile("ldmatrix.sync.aligned.m8n8.x4.trans.shared.b16 {%0,%1,%2,%3}, [%4];"
        : "=r"(r0), "=r"(r1), "=r"(r2), "=r"(r3) : "r"(addr));
}
__device__ __forceinline__ void ldsm2t(uint32_t& r0, uint32_t& r1, uint32_t addr)
{
    asm volatile("ldmatrix.sync.aligned.m8n8.x2.trans.shared.b16 {%0,%1}, [%2];"
        : "=r"(r0), "=r"(r1) : "r"(addr));
}
__device__ __forceinline__ uint32_t pack2h(float lo, float hi) {
    uint32_t r;
    asm("cvt.rn.f16x2.f32 %0, %1, %2;" : "=r"(r) : "f"(hi), "f"(lo));
    return r;
}
__device__ __forceinline__ float ex2f(float x) {
    float r;
    asm("ex2.approx.ftz.f32 %0, %1;" : "=f"(r) : "f"(x));
    return r;
}

// ---------------------------------------------------------------------------
// fp32 -> fp16 converts
// ---------------------------------------------------------------------------
__global__ void cvt_kernel(const float* __restrict__ src,
                           __half* __restrict__ dst, int n)
{
    int i = (blockIdx.x * blockDim.x + threadIdx.x) * 8;
    if (i >= n) return;
    float4 a = *(const float4*)(src + i);
    float4 b = *(const float4*)(src + i + 4);
    uint4 o;
    o.x = pack2h(a.x, a.y); o.y = pack2h(a.z, a.w);
    o.z = pack2h(b.x, b.y); o.w = pack2h(b.z, b.w);
    *(uint4*)(dst + i) = o;
}

__global__ void cvt4_kernel(const float* __restrict__ s0,
                            const float* __restrict__ s1,
                            const float* __restrict__ s2,
                            const float* __restrict__ s3,
                            __half* __restrict__ dst, int n)
{
    const float* s = (blockIdx.y == 0) ? s0 : (blockIdx.y == 1) ? s1
                   : (blockIdx.y == 2) ? s2 : s3;
    int i = (blockIdx.x * blockDim.x + threadIdx.x) * 8;
    if (i >= n) return;
    const size_t off = (size_t)blockIdx.y * n;
    float4 a = *(const float4*)(s + i);
    float4 b = *(const float4*)(s + i + 4);
    uint4 o;
    o.x = pack2h(a.x, a.y); o.y = pack2h(a.z, a.w);
    o.z = pack2h(b.x, b.y); o.w = pack2h(b.z, b.w);
    *(uint4*)(dst + off + i) = o;
}

// ---------------------------------------------------------------------------
// GEMM, fp16 mma.sync, BK=64, 3-stage cp.async ring, 1 sync/chunk.
// CTA 128x128, 256 threads, 8 warps 2(m)x4(n), warp tile 64x32.
// mode 0: fused QKV — W fused [3072,1024]; writes fp16 Q/K/V in [B,H,T,D].
//         Q is pre-scaled by 0.125*log2(e) so attention can use ex2 directly.
// mode 1: output projection — fp32 Cout row-major, bias b0.
// ---------------------------------------------------------------------------
#define GP2 72
#define ARR2 (128*GP2*2)           // 18432 bytes per operand array
#define STG2B (2*ARR2)             // 36864 per stage
#define GEMM_SMEM2 (3*STG2B)       // 110592

__global__ __launch_bounds__(256, 2) void gemm_h(
    const __half* __restrict__ A, const __half* __restrict__ W,
    const float* __restrict__ b0, const float* __restrict__ b1,
    const float* __restrict__ b2, float* __restrict__ Cout, int mode)
{
    extern __shared__ char sm[];
    const uint32_t sb = smem_u32(sm);
    const int tid = threadIdx.x, lane = tid & 31, wid = tid >> 5;
    const int wm = wid & 1, wn = wid >> 1;
    const int m0 = blockIdx.y * 128, n0 = blockIdx.x * 128;

    const int srow = tid >> 1, scol = (tid & 1) * 32;
    const uint32_t soff = (uint32_t)(srow * GP2 + scol) * 2;
    const __half* Ar = A + (size_t)(m0 + srow) * Cdim + scol;
    const __half* Wr = W + (size_t)(n0 + srow) * Cdim + scol;

#define STG(kc, slot) do {                                        \
        uint32_t st_ = sb + (slot) * STG2B;                       \
        cp16(st_ + soff,               Ar + (kc));                \
        cp16(st_ + soff + 16,          Ar + (kc) + 8);            \
        cp16(st_ + soff + 32,          Ar + (kc) + 16);           \
        cp16(st_ + soff + 48,          Ar + (kc) + 24);           \
        cp16(st_ + ARR2 + soff,        Wr + (kc));                \
        cp16(st_ + ARR2 + soff + 16,   Wr + (kc) + 8);            \
        cp16(st_ + ARR2 + soff + 32,   Wr + (kc) + 16);           \
        cp16(st_ + ARR2 + soff + 48,   Wr + (kc) + 24);           \
        cp_commit();                                              \
    } while (0)

    float acc[4][4][4];
#pragma unroll
    for (int a = 0; a < 4; a++)
#pragma unroll
        for (int b = 0; b < 4; b++)
#pragma unroll
            for (int c = 0; c < 4; c++) acc[a][b][c] = 0.f;

    STG(0, 0); STG(64, 1);

    int slot_next = 2;
    for (int kt = 0; kt < 16; kt++) {
        if (kt < 14) cp_wait<1>(); else cp_wait<0>();
        __syncthreads();

        const int sl = kt - (kt / 3) * 3;   // kt mod 3
        const uint32_t stb = sb + sl * STG2B;

#pragma unroll
        for (int s = 0; s < 4; s++) {
            const uint32_t cg = s * 16 + ((lane >> 4) << 3);
            uint32_t bf[2][4], af[4][4];
#pragma unroll
            for (int ntp = 0; ntp < 2; ntp++)
                ldsm4(bf[ntp][0], bf[ntp][1], bf[ntp][2], bf[ntp][3],
                      stb + ARR2 +
                      ((wn * 32 + ntp * 16 + (lane & 15)) * GP2 + cg) * 2);
#pragma unroll
            for (int mt = 0; mt < 4; mt++)
                ldsm4(af[mt][0], af[mt][1], af[mt][2], af[mt][3],
                      stb + ((wm * 64 + mt * 16 + (lane & 15)) * GP2 + cg) * 2);
#pragma unroll
            for (int mt = 0; mt < 4; mt++)
#pragma unroll
                for (int nt = 0; nt < 4; nt++) {
                    float* c = acc[mt][nt];
                    mma_h(c[0], c[1], c[2], c[3],
                          af[mt][0], af[mt][1], af[mt][2], af[mt][3],
                          bf[nt >> 1][nt & 1], bf[nt >> 1][(nt & 1) + 2]);
                }
        }
        if (kt + 2 < 16) {
            STG((kt + 2) * 64, slot_next);
            slot_next = (slot_next == 2) ? 0 : slot_next + 1;
        }
    }
#undef STG

    // epilogue
    const int mat = n0 >> 10;  // constant per CTA (mode 0)
    const float* bb = (mat == 0) ? b0 : (mat == 1) ? b1 : b2;
    __half* dsth = (mat == 0) ? g_Qh : (mat == 1) ? g_Kh : g_Vh;
    // Q scale folds 1/sqrt(D) AND log2(e) so attention uses ex2 directly
    const float scale = (mat == 0) ? 0.125f * 1.4426950408889634f : 1.0f;

#pragma unroll
    for (int mt = 0; mt < 4; mt++) {
#pragma unroll
        for (int nt = 0; nt < 4; nt++) {
            float* c = acc[mt][nt];
            const int row = m0 + wm * 64 + mt * 16 + (lane >> 2);
            const int col = n0 + wn * 32 + nt * 8 + 2 * (lane & 3);
            if (mode == 1) {
                const float bv0 = b0[col], bv1 = b0[col + 1];
                *(float2*)(Cout + (size_t)row * Cdim + col) =
                    make_float2(c[0] + bv0, c[1] + bv1);
                *(float2*)(Cout + (size_t)(row + 8) * Cdim + col) =
                    make_float2(c[2] + bv0, c[3] + bv1);
            } else {
                const int mc = col & 1023;
                const float bv0 = bb[mc], bv1 = bb[mc + 1];
                const float v00 = (c[0] + bv0) * scale, v01 = (c[1] + bv1) * scale;
                const float v10 = (c[2] + bv0) * scale, v11 = (c[3] + bv1) * scale;
                const int hh = mc >> 6, d = mc & 63;
                const int bb0 = row >> 11, t0 = row & 2047;
                const int bb1 = (row + 8) >> 11, t1 = (row + 8) & 2047;
                const size_t i0 = (((size_t)(bb0 * Hh + hh)) * Tq + t0) * Dd + d;
                const size_t i1 = (((size_t)(bb1 * Hh + hh)) * Tq + t1) * Dd + d;
                *(uint32_t*)(dsth + i0) = pack2h(v00, v01);
                *(uint32_t*)(dsth + i1) = pack2h(v10, v11);
            }
        }
    }
}

// ---------------------------------------------------------------------------
// Flash attention, fp16 mma.sync, static softmax (exp via raw ex2; Q carries
// the 0.125*log2e scale). Tile loop restructured into per-key-group stages
// (S-mma -> ex2 -> pack -> PV-mma per 16 keys) so tensor and MUFU phases of
// adjacent groups overlap instead of serializing.
// 3-buffer K/V ring, single __syncthreads per tile, ones-column row sums,
// all-ones mask fast path. CTA: 256 threads (8 warps), 128 queries.
// ---------------------------------------------------------------------------
#define QP 72
#define QTILE (128*QP*2)           // 18432
#define KVARR (64*QP*2)            // 9216
#define OFF_Q 0
#define OFF_KB(s) (QTILE + (s)*2*KVARR)
#define OFF_VB(s) (QTILE + (s)*2*KVARR + KVARR)
#define OFF_MK (QTILE + 6*KVARR)
#define ATT_SMEM_B (OFF_MK + 3*64*4)   // 74496

__global__ __launch_bounds__(256, 2) void attn_h(const int* __restrict__ mask)
{
    extern __shared__ char sm[];
    const uint32_t sb = smem_u32(sm);
    const int tid = threadIdx.x, lane = tid & 31, wid = tid >> 5;
    const int bh = blockIdx.y;
    const int b  = bh >> 4, h = bh & 15;
    const int q0 = blockIdx.x * 128;
    int* Mk = (int*)(sm + OFF_MK);

    // ones columns (V cols 64..71, all 3 buffers) — written once.
    if (tid < 192) {
        const int s = tid >> 6, row = tid & 63;
        uint32_t* p = (uint32_t*)(sm + OFF_VB(s) + (row * QP + 64) * 2);
        p[0] = 0x3C003C00u; p[1] = 0x3C003C00u;
        p[2] = 0x3C003C00u; p[3] = 0x3C003C00u;
    }

    // Q staging: 128 rows, 2 threads/row, 4 cp16 each
    {
        const int qrow = tid >> 1, qcol = (tid & 1) * 32;
        const uint32_t qoff = (uint32_t)(qrow * QP + qcol) * 2;
        const __half* Qg = g_Qh + ((size_t)bh * Tq + q0 + qrow) * Dd + qcol;
#pragma unroll
        for (int j = 0; j < 4; j++)
            cp16(sb + OFF_Q + qoff + j * 16, Qg + j * 8);
        cp_commit();
    }

    // K/V staging coords: 64 rows, 4 threads/row, 2 cp16 per array
    const int krow = tid >> 2, kcol = (tid & 3) * 16;
    const uint32_t koff = (uint32_t)(krow * QP + kcol) * 2;

#define STAGEKV(kt, slot) do {                                                 \
        const __half* Kg_ = g_Kh + ((size_t)bh * Tq + (kt) * 64 + krow) * Dd + kcol; \
        const __half* Vg_ = g_Vh + ((size_t)bh * Tq + (kt) * 64 + krow) * Dd + kcol; \
        cp16(sb + OFF_KB(slot) + koff,      Kg_);                              \
        cp16(sb + OFF_KB(slot) + koff + 16, Kg_ + 8);                          \
        cp16(sb + OFF_VB(slot) + koff,      Vg_);                              \
        cp16(sb + OFF_VB(slot) + koff + 16, Vg_ + 8);                          \
        if (tid < 64) Mk[(slot) * 64 + tid] = mask[b * Tq + (kt) * 64 + tid];  \
        cp_commit();                                                           \
    } while (0)

    STAGEKV(0, 0);
    STAGEKV(1, 1);
    cp_wait<2>();       // Q landed
    __syncthreads();

    // hoist Q fragments (loop-invariant)
    uint32_t qf[4][4];
#pragma unroll
    for (int kd = 0; kd < 4; kd++)
        ldsm4(qf[kd][0], qf[kd][1], qf[kd][2], qf[kd][3],
              sb + OFF_Q +
              ((wid * 16 + (lane & 15)) * QP + kd * 16 + ((lane >> 4) << 3)) * 2);

    float o[8][4];
#pragma unroll
    for (int nt = 0; nt < 8; nt++)
#pragma unroll
        for (int c = 0; c < 4; c++) o[nt][c] = 0.f;
    float ssum[4] = {0.f, 0.f, 0.f, 0.f};

    const int NT = Tq / 64;   // 32
    int r = 0, snext = 2;
    for (int kt = 0; kt < NT; kt++) {
        if (kt < NT - 1) cp_wait<1>(); else cp_wait<0>();
        __syncthreads();
        if (kt + 2 < NT) {
            STAGEKV(kt + 2, snext);
            snext = (snext == 2) ? 0 : snext + 1;
        }

        const int* mk = Mk + r * 64;
        const bool allone = __all_sync(0xffffffffu,
                (mk[lane] != 0) & (mk[lane + 32] != 0));
        const int c0 = 2 * (lane & 3);
        const uint32_t kbase = sb + OFF_KB(r) + ((lane & 15) * QP + ((lane >> 4) << 3)) * 2;
        const uint32_t vbase = sb + OFF_VB(r) + ((lane & 15) * QP + ((lane >> 4) << 3)) * 2;
        const uint32_t ubase = sb + OFF_VB(r) + ((lane & 15) * QP + 64) * 2;

        // per-key-group pipeline: S(g) -> ex2(g) -> PV(g); S(g+1) is
        // independent of ex2/PV(g) so tensor & MUFU overlap across groups.
#pragma unroll
        for (int g = 0; g < 4; g++) {
            // ---- S for keys [16g, 16g+16) ----
            float s0[4] = {0.f, 0.f, 0.f, 0.f};
            float s1[4] = {0.f, 0.f, 0.f, 0.f};
#pragma unroll
            for (int kd = 0; kd < 4; kd++) {
                uint32_t k0, k1, k2, k3;
                ldsm4(k0, k1, k2, k3, kbase + (g * 16 * QP + kd * 16) * 2);
                mma_h(s0[0], s0[1], s0[2], s0[3],
                      qf[kd][0], qf[kd][1], qf[kd][2], qf[kd][3], k0, k2);
                mma_h(s1[0], s1[1], s1[2], s1[3],
                      qf[kd][0], qf[kd][1], qf[kd][2], qf[kd][3], k1, k3);
            }

            // ---- mask ----
            if (!allone) {
                if (!mk[g * 16 + c0])         { s0[0] = -1e30f; s0[2] = -1e30f; }
                if (!mk[g * 16 + c0 + 1])     { s0[1] = -1e30f; s0[3] = -1e30f; }
                if (!mk[g * 16 + 8 + c0])     { s1[0] = -1e30f; s1[2] = -1e30f; }
                if (!mk[g * 16 + 8 + c0 + 1]) { s1[1] = -1e30f; s1[3] = -1e30f; }
            }

            // ---- P = 2^S (Q carries log2e scale) ----
            s0[0] = ex2f(s0[0]); s0[1] = ex2f(s0[1]);
            s0[2] = ex2f(s0[2]); s0[3] = ex2f(s0[3]);
            s1[0] = ex2f(s1[0]); s1[1] = ex2f(s1[1]);
            s1[2] = ex2f(s1[2]); s1[3] = ex2f(s1[3]);

            const uint32_t pa0 = pack2h(s0[0], s0[1]);
            const uint32_t pa1 = pack2h(s0[2], s0[3]);
            const uint32_t pa2 = pack2h(s1[0], s1[1]);
            const uint32_t pa3 = pack2h(s1[2], s1[3]);

            // ---- PV for key chunk g (+ ones column row sums) ----
            uint32_t u0, u1;
            ldsm2t(u0, u1, ubase + g * 16 * QP * 2);
            mma_h(ssum[0], ssum[1], ssum[2], ssum[3], pa0, pa1, pa2, pa3, u0, u1);
#pragma unroll
            for (int ntp = 0; ntp < 4; ntp++) {
                uint32_t v0, v1, v2, v3;
                ldsm4t(v0, v1, v2, v3, vbase + (g * 16 * QP + ntp * 16) * 2);
                float* oa = o[2 * ntp];
                float* ob = o[2 * ntp + 1];
                mma_h(oa[0], oa[1], oa[2], oa[3], pa0, pa1, pa2, pa3, v0, v1);
                mma_h(ob[0], ob[1], ob[2], ob[3], pa0, pa1, pa2, pa3, v2, v3);
            }
        }
        r = (r == 2) ? 0 : r + 1;
    }
#undef STAGEKV

    // ---- finalize: ssum fragment holds exact row sums ----
    const float inv0 = 1.0f / ssum[0], inv1 = 1.0f / ssum[2];
    const int gr0 = q0 + wid * 16 + (lane >> 2);
#pragma unroll
    for (int nt = 0; nt < 8; nt++) {
        const int col = h * Dd + nt * 8 + 2 * (lane & 3);
        const size_t i0 = ((size_t)b * Tq + gr0) * Cdim + col;
        const size_t i1 = ((size_t)b * Tq + gr0 + 8) * Cdim + col;
        *(uint32_t*)(g_Oh + i0) = pack2h(o[nt][0] * inv0, o[nt][1] * inv0);
        *(uint32_t*)(g_Oh + i1) = pack2h(o[nt][2] * inv1, o[nt][3] * inv1);
    }
}

// ---------------------------------------------------------------------------
extern "C" void kernel_launch(void* const* d_in, const int* in_sizes, int n_in,
                              void* d_out, int out_size)
{
    (void)in_sizes; (void)n_in; (void)out_size;
    const float* x    = (const float*)d_in[0];
    const int*   mask = (const int*)d_in[1];
    const float* Wq = (const float*)d_in[2];
    const float* bq = (const float*)d_in[3];
    const float* Wk = (const float*)d_in[4];
    const float* bk = (const float*)d_in[5];
    const float* Wv = (const float*)d_in[6];
    const float* bv = (const float*)d_in[7];
    const float* Wp = (const float*)d_in[8];
    const float* bp = (const float*)d_in[9];
    float* out = (float*)d_out;

    static bool init = false;
    static __half *xh, *wh, *oh;
    if (!init) {
        cudaFuncSetAttribute(gemm_h,
            cudaFuncAttributeMaxDynamicSharedMemorySize, GEMM_SMEM2);
        cudaFuncSetAttribute(attn_h,
            cudaFuncAttributeMaxDynamicSharedMemorySize, ATT_SMEM_B);
        cudaGetSymbolAddress((void**)&xh, g_xh);
        cudaGetSymbolAddress((void**)&wh, g_Wh);
        cudaGetSymbolAddress((void**)&oh, g_Oh);
        init = true;
    }

    const int NX = Mrows * Cdim;   // 4194304
    const int NW = Cdim * Cdim;    // 1048576
    const size_t WN = (size_t)NW;

    cvt_kernel<<<NX / 2048, 256>>>(x, xh, NX);
    {
        dim3 g(NW / 2048, 4);
        cvt4_kernel<<<g, 256>>>(Wq, Wk, Wv, Wp, wh, NW);
    }

    // fused QKV projection: N = 3072 over packed Wq|Wk|Wv
    {
        dim3 g(3 * Cdim / 128, Mrows / 128);  // (24, 32)
        gemm_h<<<g, 256, GEMM_SMEM2>>>(xh, wh, bq, bk, bv, nullptr, 0);
    }

    {
        dim3 g(Tq / 128, Bsz * Hh);           // (16, 32)
        attn_h<<<g, 256, ATT_SMEM_B>>>(mask);
    }

    // output projection
    {
        dim3 g(Cdim / 128, Mrows / 128);      // (8, 32)
        gemm_h<<<g, 256, GEMM_SMEM2>>>(oh, wh + 3 * WN, bp, bp, bp, out, 1);
    }
}

// round 10
// speedup vs baseline: 1.5419x; 1.5419x over previous
#include <cuda_runtime.h>
#include <cuda_fp16.h>
#include <math.h>
#include <stdint.h>

// Problem constants
#define Bsz 2
#define Tq  2048
#define Cdim 1024
#define Hh  16
#define Dd  64
#define Mrows (Bsz*Tq)   // 4096

// ---------------------------------------------------------------------------
// Device-global scratch (sanctioned no-alloc path)
// ---------------------------------------------------------------------------
__device__ __align__(16) __half g_xh[Mrows*Cdim];
__device__ __align__(16) __half g_Wh[4*Cdim*Cdim];   // Wq,Wk,Wv,Wp packed
__device__ __align__(16) __half g_Qh[Mrows*Cdim];
__device__ __align__(16) __half g_Kh[Mrows*Cdim];
__device__ __align__(16) __half g_Vh[Mrows*Cdim];
__device__ __align__(16) __half g_Oh[Mrows*Cdim];

// ---------------------------------------------------------------------------
// Helpers (family-portable ISA)
// ---------------------------------------------------------------------------
__device__ __forceinline__ uint32_t smem_u32(const void* p) {
    uint32_t a;
    asm("{ .reg .u64 t; cvta.to.shared.u64 t, %1; cvt.u32.u64 %0, t; }"
        : "=r"(a) : "l"(p));
    return a;
}
__device__ __forceinline__ void cp16(uint32_t dst, const void* src) {
    asm volatile("cp.async.cg.shared.global [%0], [%1], 16;"
                 :: "r"(dst), "l"(src));
}
__device__ __forceinline__ void cp_commit() {
    asm volatile("cp.async.commit_group;");
}
template<int N> __device__ __forceinline__ void cp_wait() {
    asm volatile("cp.async.wait_group %0;" :: "n"(N));
}
__device__ __forceinline__ void mma_h(
    float& c0, float& c1, float& c2, float& c3,
    uint32_t a0, uint32_t a1, uint32_t a2, uint32_t a3,
    uint32_t b0, uint32_t b1)
{
    asm volatile(
        "mma.sync.aligned.m16n8k16.row.col.f32.f16.f16.f32 "
        "{%0,%1,%2,%3}, {%4,%5,%6,%7}, {%8,%9}, {%0,%1,%2,%3};"
        : "+f"(c0), "+f"(c1), "+f"(c2), "+f"(c3)
        : "r"(a0), "r"(a1), "r"(a2), "r"(a3), "r"(b0), "r"(b1));
}
__device__ __forceinline__ void ldsm4(
    uint32_t& r0, uint32_t& r1, uint32_t& r2, uint32_t& r3, uint32_t addr)
{
    asm volatile("ldmatrix.sync.aligned.m8n8.x4.shared.b16 {%0,%1,%2,%3}, [%4];"
        : "=r"(r0), "=r"(r1), "=r"(r2), "=r"(r3) : "r"(addr));
}
__device__ __forceinline__ void ldsm4t(
    uint32_t& r0, uint32_t& r1, uint32_t& r2, uint32_t& r3, uint32_t addr)
{
    asm volatile("ldmatrix.sync.aligned.m8n8.x4.trans.shared.b16 {%0,%1,%2,%3}, [%4];"
        : "=r"(r0), "=r"(r1), "=r"(r2), "=r"(r3) : "r"(addr));
}
__device__ __forceinline__ void ldsm2t(uint32_t& r0, uint32_t& r1, uint32_t addr)
{
    asm volatile("ldmatrix.sync.aligned.m8n8.x2.trans.shared.b16 {%0,%1}, [%2];"
        : "=r"(r0), "=r"(r1) : "r"(addr));
}
__device__ __forceinline__ uint32_t pack2h(float lo, float hi) {
    uint32_t r;
    asm("cvt.rn.f16x2.f32 %0, %1, %2;" : "=r"(r) : "f"(hi), "f"(lo));
    return r;
}
__device__ __forceinline__ float ex2f(float x) {
    float r;
    asm("ex2.approx.ftz.f32 %0, %1;" : "=f"(r) : "f"(x));
    return r;
}

// ---------------------------------------------------------------------------
// fp32 -> fp16 converts
// ---------------------------------------------------------------------------
__global__ void cvt_kernel(const float* __restrict__ src,
                           __half* __restrict__ dst, int n)
{
    int i = (blockIdx.x * blockDim.x + threadIdx.x) * 8;
    if (i >= n) return;
    float4 a = *(const float4*)(src + i);
    float4 b = *(const float4*)(src + i + 4);
    uint4 o;
    o.x = pack2h(a.x, a.y); o.y = pack2h(a.z, a.w);
    o.z = pack2h(b.x, b.y); o.w = pack2h(b.z, b.w);
    *(uint4*)(dst + i) = o;
}

__global__ void cvt4_kernel(const float* __restrict__ s0,
                            const float* __restrict__ s1,
                            const float* __restrict__ s2,
                            const float* __restrict__ s3,
                            __half* __restrict__ dst, int n)
{
    const float* s = (blockIdx.y == 0) ? s0 : (blockIdx.y == 1) ? s1
                   : (blockIdx.y == 2) ? s2 : s3;
    int i = (blockIdx.x * blockDim.x + threadIdx.x) * 8;
    if (i >= n) return;
    const size_t off = (size_t)blockIdx.y * n;
    float4 a = *(const float4*)(s + i);
    float4 b = *(const float4*)(s + i + 4);
    uint4 o;
    o.x = pack2h(a.x, a.y); o.y = pack2h(a.z, a.w);
    o.z = pack2h(b.x, b.y); o.w = pack2h(b.z, b.w);
    *(uint4*)(dst + off + i) = o;
}

// ---------------------------------------------------------------------------
// GEMM, fp16 mma.sync, BK=64, 3-stage cp.async ring, 1 sync/chunk.
// CTA 128x128, 256 threads, 8 warps 2(m)x4(n), warp tile 64x32.
// mode 0: fused QKV — W fused [3072,1024]; writes fp16 Q/K/V in [B,H,T,D].
//         Q is pre-scaled by 0.125*log2(e) so attention uses ex2 directly.
// mode 1: output projection — fp32 Cout row-major, bias b0.
// ---------------------------------------------------------------------------
#define GP2 72
#define ARR2 (128*GP2*2)           // 18432 bytes per operand array
#define STG2B (2*ARR2)             // 36864 per stage
#define GEMM_SMEM2 (3*STG2B)       // 110592

__global__ __launch_bounds__(256, 2) void gemm_h(
    const __half* __restrict__ A, const __half* __restrict__ W,
    const float* __restrict__ b0, const float* __restrict__ b1,
    const float* __restrict__ b2, float* __restrict__ Cout, int mode)
{
    extern __shared__ char sm[];
    const uint32_t sb = smem_u32(sm);
    const int tid = threadIdx.x, lane = tid & 31, wid = tid >> 5;
    const int wm = wid & 1, wn = wid >> 1;
    const int m0 = blockIdx.y * 128, n0 = blockIdx.x * 128;

    const int srow = tid >> 1, scol = (tid & 1) * 32;
    const uint32_t soff = (uint32_t)(srow * GP2 + scol) * 2;
    const __half* Ar = A + (size_t)(m0 + srow) * Cdim + scol;
    const __half* Wr = W + (size_t)(n0 + srow) * Cdim + scol;

#define STG(kc, slot) do {                                        \
        uint32_t st_ = sb + (slot) * STG2B;                       \
        cp16(st_ + soff,               Ar + (kc));                \
        cp16(st_ + soff + 16,          Ar + (kc) + 8);            \
        cp16(st_ + soff + 32,          Ar + (kc) + 16);           \
        cp16(st_ + soff + 48,          Ar + (kc) + 24);           \
        cp16(st_ + ARR2 + soff,        Wr + (kc));                \
        cp16(st_ + ARR2 + soff + 16,   Wr + (kc) + 8);            \
        cp16(st_ + ARR2 + soff + 32,   Wr + (kc) + 16);           \
        cp16(st_ + ARR2 + soff + 48,   Wr + (kc) + 24);           \
        cp_commit();                                              \
    } while (0)

    float acc[4][4][4];
#pragma unroll
    for (int a = 0; a < 4; a++)
#pragma unroll
        for (int b = 0; b < 4; b++)
#pragma unroll
            for (int c = 0; c < 4; c++) acc[a][b][c] = 0.f;

    STG(0, 0); STG(64, 1);

    int slot_next = 2;
    for (int kt = 0; kt < 16; kt++) {
        if (kt < 14) cp_wait<1>(); else cp_wait<0>();
        __syncthreads();

        const int sl = kt - (kt / 3) * 3;   // kt mod 3
        const uint32_t stb = sb + sl * STG2B;

#pragma unroll
        for (int s = 0; s < 4; s++) {
            const uint32_t cg = s * 16 + ((lane >> 4) << 3);
            uint32_t bf[2][4], af[4][4];
#pragma unroll
            for (int ntp = 0; ntp < 2; ntp++)
                ldsm4(bf[ntp][0], bf[ntp][1], bf[ntp][2], bf[ntp][3],
                      stb + ARR2 +
                      ((wn * 32 + ntp * 16 + (lane & 15)) * GP2 + cg) * 2);
#pragma unroll
            for (int mt = 0; mt < 4; mt++)
                ldsm4(af[mt][0], af[mt][1], af[mt][2], af[mt][3],
                      stb + ((wm * 64 + mt * 16 + (lane & 15)) * GP2 + cg) * 2);
#pragma unroll
            for (int mt = 0; mt < 4; mt++)
#pragma unroll
                for (int nt = 0; nt < 4; nt++) {
                    float* c = acc[mt][nt];
                    mma_h(c[0], c[1], c[2], c[3],
                          af[mt][0], af[mt][1], af[mt][2], af[mt][3],
                          bf[nt >> 1][nt & 1], bf[nt >> 1][(nt & 1) + 2]);
                }
        }
        if (kt + 2 < 16) {
            STG((kt + 2) * 64, slot_next);
            slot_next = (slot_next == 2) ? 0 : slot_next + 1;
        }
    }
#undef STG

    // epilogue
    const int mat = n0 >> 10;  // constant per CTA (mode 0)
    const float* bb = (mat == 0) ? b0 : (mat == 1) ? b1 : b2;
    __half* dsth = (mat == 0) ? g_Qh : (mat == 1) ? g_Kh : g_Vh;
    // Q scale folds 1/sqrt(D) AND log2(e) so attention uses ex2 directly
    const float scale = (mat == 0) ? 0.125f * 1.4426950408889634f : 1.0f;

#pragma unroll
    for (int mt = 0; mt < 4; mt++) {
#pragma unroll
        for (int nt = 0; nt < 4; nt++) {
            float* c = acc[mt][nt];
            const int row = m0 + wm * 64 + mt * 16 + (lane >> 2);
            const int col = n0 + wn * 32 + nt * 8 + 2 * (lane & 3);
            if (mode == 1) {
                const float bv0 = b0[col], bv1 = b0[col + 1];
                *(float2*)(Cout + (size_t)row * Cdim + col) =
                    make_float2(c[0] + bv0, c[1] + bv1);
                *(float2*)(Cout + (size_t)(row + 8) * Cdim + col) =
                    make_float2(c[2] + bv0, c[3] + bv1);
            } else {
                const int mc = col & 1023;
                const float bv0 = bb[mc], bv1 = bb[mc + 1];
                const float v00 = (c[0] + bv0) * scale, v01 = (c[1] + bv1) * scale;
                const float v10 = (c[2] + bv0) * scale, v11 = (c[3] + bv1) * scale;
                const int hh = mc >> 6, d = mc & 63;
                const int bb0 = row >> 11, t0 = row & 2047;
                const int bb1 = (row + 8) >> 11, t1 = (row + 8) & 2047;
                const size_t i0 = (((size_t)(bb0 * Hh + hh)) * Tq + t0) * Dd + d;
                const size_t i1 = (((size_t)(bb1 * Hh + hh)) * Tq + t1) * Dd + d;
                *(uint32_t*)(dsth + i0) = pack2h(v00, v01);
                *(uint32_t*)(dsth + i1) = pack2h(v10, v11);
            }
        }
    }
}

// ---------------------------------------------------------------------------
// Flash attention, fp16 mma.sync, static softmax. ROUND-8 STRUCTURE
// (full S phase -> exp phase -> full PV phase; long independent MMA runs,
// cross-warp drift hides the MUFU burst). Only change vs round 8: exp is a
// bare ex2 because Q carries the 0.125*log2e scale from the projection.
// 3-buffer K/V ring, single __syncthreads per tile, ones-column row sums,
// all-ones mask fast path. CTA: 256 threads (8 warps), 128 queries.
// ---------------------------------------------------------------------------
#define QP 72
#define QTILE (128*QP*2)           // 18432
#define KVARR (64*QP*2)            // 9216
#define OFF_Q 0
#define OFF_KB(s) (QTILE + (s)*2*KVARR)
#define OFF_VB(s) (QTILE + (s)*2*KVARR + KVARR)
#define OFF_MK (QTILE + 6*KVARR)
#define ATT_SMEM_B (OFF_MK + 3*64*4)   // 74496

__global__ __launch_bounds__(256, 2) void attn_h(const int* __restrict__ mask)
{
    extern __shared__ char sm[];
    const uint32_t sb = smem_u32(sm);
    const int tid = threadIdx.x, lane = tid & 31, wid = tid >> 5;
    const int bh = blockIdx.y;
    const int b  = bh >> 4, h = bh & 15;
    const int q0 = blockIdx.x * 128;
    int* Mk = (int*)(sm + OFF_MK);

    // ones columns (V cols 64..71, all 3 buffers) — written once; cp.async
    // staging only touches cols 0..63, so these persist for the whole kernel.
    if (tid < 192) {
        const int s = tid >> 6, row = tid & 63;
        uint32_t* p = (uint32_t*)(sm + OFF_VB(s) + (row * QP + 64) * 2);
        p[0] = 0x3C003C00u; p[1] = 0x3C003C00u;
        p[2] = 0x3C003C00u; p[3] = 0x3C003C00u;
    }

    // Q staging: 128 rows, 2 threads/row, 4 cp16 each
    {
        const int qrow = tid >> 1, qcol = (tid & 1) * 32;
        const uint32_t qoff = (uint32_t)(qrow * QP + qcol) * 2;
        const __half* Qg = g_Qh + ((size_t)bh * Tq + q0 + qrow) * Dd + qcol;
#pragma unroll
        for (int j = 0; j < 4; j++)
            cp16(sb + OFF_Q + qoff + j * 16, Qg + j * 8);
        cp_commit();
    }

    // K/V staging coords: 64 rows, 4 threads/row, 2 cp16 per array
    const int krow = tid >> 2, kcol = (tid & 3) * 16;
    const uint32_t koff = (uint32_t)(krow * QP + kcol) * 2;

#define STAGEKV(kt, slot) do {                                                 \
        const __half* Kg_ = g_Kh + ((size_t)bh * Tq + (kt) * 64 + krow) * Dd + kcol; \
        const __half* Vg_ = g_Vh + ((size_t)bh * Tq + (kt) * 64 + krow) * Dd + kcol; \
        cp16(sb + OFF_KB(slot) + koff,      Kg_);                              \
        cp16(sb + OFF_KB(slot) + koff + 16, Kg_ + 8);                          \
        cp16(sb + OFF_VB(slot) + koff,      Vg_);                              \
        cp16(sb + OFF_VB(slot) + koff + 16, Vg_ + 8);                          \
        if (tid < 64) Mk[(slot) * 64 + tid] = mask[b * Tq + (kt) * 64 + tid];  \
        cp_commit();                                                           \
    } while (0)

    STAGEKV(0, 0);
    STAGEKV(1, 1);
    cp_wait<2>();       // Q landed (pending: s0, s1)
    __syncthreads();

    // hoist Q fragments (loop-invariant): warp covers rows wid*16..wid*16+15
    uint32_t qf[4][4];
#pragma unroll
    for (int ks = 0; ks < 4; ks++)
        ldsm4(qf[ks][0], qf[ks][1], qf[ks][2], qf[ks][3],
              sb + OFF_Q +
              ((wid * 16 + (lane & 15)) * QP + ks * 16 + ((lane >> 4) << 3)) * 2);

    float o[8][4];
#pragma unroll
    for (int nt = 0; nt < 8; nt++)
#pragma unroll
        for (int c = 0; c < 4; c++) o[nt][c] = 0.f;
    float ssum[4] = {0.f, 0.f, 0.f, 0.f};   // row-sum fragment (ones-col MMA)

    const int NT = Tq / 64;   // 32
    int r = 0, snext = 2;
    for (int kt = 0; kt < NT; kt++) {
        if (kt < NT - 1) cp_wait<1>(); else cp_wait<0>();
        __syncthreads();   // buffer r ready; also releases slot snext (read at kt-1)
        if (kt + 2 < NT) {
            STAGEKV(kt + 2, snext);
            snext = (snext == 2) ? 0 : snext + 1;
        }

        // ---- S = Q K^T ----
        float s[8][4];
#pragma unroll
        for (int nt = 0; nt < 8; nt++)
#pragma unroll
            for (int c = 0; c < 4; c++) s[nt][c] = 0.f;

#pragma unroll
        for (int ks = 0; ks < 4; ks++) {
#pragma unroll
            for (int ntp = 0; ntp < 4; ntp++) {
                uint32_t k0, k1, k2, k3;
                ldsm4(k0, k1, k2, k3,
                      sb + OFF_KB(r) +
                      ((ntp * 16 + (lane & 15)) * QP + ks * 16 + ((lane >> 4) << 3)) * 2);
                float* sa = s[2 * ntp];
                float* sc = s[2 * ntp + 1];
                mma_h(sa[0], sa[1], sa[2], sa[3],
                      qf[ks][0], qf[ks][1], qf[ks][2], qf[ks][3], k0, k2);
                mma_h(sc[0], sc[1], sc[2], sc[3],
                      qf[ks][0], qf[ks][1], qf[ks][2], qf[ks][3], k1, k3);
            }
        }

        // ---- mask (warp-uniform all-ones fast path) ----
        const int* mk = Mk + r * 64;
        const bool allone = __all_sync(0xffffffffu,
                (mk[lane] != 0) & (mk[lane + 32] != 0));
        if (!allone) {
            const int c0 = 2 * (lane & 3);
#pragma unroll
            for (int nt = 0; nt < 8; nt++) {
                if (!mk[nt * 8 + c0])     { s[nt][0] = -1e30f; s[nt][2] = -1e30f; }
                if (!mk[nt * 8 + c0 + 1]) { s[nt][1] = -1e30f; s[nt][3] = -1e30f; }
            }
        }

        // ---- static softmax: P = 2^S (Q carries log2e; bare MUFU) ----
#pragma unroll
        for (int nt = 0; nt < 8; nt++) {
            s[nt][0] = ex2f(s[nt][0]);
            s[nt][1] = ex2f(s[nt][1]);
            s[nt][2] = ex2f(s[nt][2]);
            s[nt][3] = ex2f(s[nt][3]);
        }

        // ---- O += P V ; ssum += P @ ones ----
#pragma unroll
        for (int ks = 0; ks < 4; ks++) {
            uint32_t pa0 = pack2h(s[2 * ks][0],     s[2 * ks][1]);
            uint32_t pa1 = pack2h(s[2 * ks][2],     s[2 * ks][3]);
            uint32_t pa2 = pack2h(s[2 * ks + 1][0], s[2 * ks + 1][1]);
            uint32_t pa3 = pack2h(s[2 * ks + 1][2], s[2 * ks + 1][3]);

            uint32_t u0, u1;   // ones-column B fragment (cols 64..71)
            ldsm2t(u0, u1,
                   sb + OFF_VB(r) + ((ks * 16 + (lane & 15)) * QP + 64) * 2);
            mma_h(ssum[0], ssum[1], ssum[2], ssum[3], pa0, pa1, pa2, pa3, u0, u1);

#pragma unroll
            for (int ntp = 0; ntp < 4; ntp++) {
                uint32_t v0, v1, v2, v3;
                ldsm4t(v0, v1, v2, v3,
                       sb + OFF_VB(r) +
                       ((ks * 16 + (lane & 15)) * QP + ntp * 16 + ((lane >> 4) << 3)) * 2);
                float* oa = o[2 * ntp];
                float* ob = o[2 * ntp + 1];
                mma_h(oa[0], oa[1], oa[2], oa[3], pa0, pa1, pa2, pa3, v0, v1);
                mma_h(ob[0], ob[1], ob[2], ob[3], pa0, pa1, pa2, pa3, v2, v3);
            }
        }
        r = (r == 2) ? 0 : r + 1;
    }
#undef STAGEKV

    // ---- finalize: ssum fragment already holds exact row sums ----
    const float inv0 = 1.0f / ssum[0], inv1 = 1.0f / ssum[2];
    const int gr0 = q0 + wid * 16 + (lane >> 2);
#pragma unroll
    for (int nt = 0; nt < 8; nt++) {
        const int col = h * Dd + nt * 8 + 2 * (lane & 3);
        const size_t i0 = ((size_t)b * Tq + gr0) * Cdim + col;
        const size_t i1 = ((size_t)b * Tq + gr0 + 8) * Cdim + col;
        *(uint32_t*)(g_Oh + i0) = pack2h(o[nt][0] * inv0, o[nt][1] * inv0);
        *(uint32_t*)(g_Oh + i1) = pack2h(o[nt][2] * inv1, o[nt][3] * inv1);
    }
}

// ---------------------------------------------------------------------------
extern "C" void kernel_launch(void* const* d_in, const int* in_sizes, int n_in,
                              void* d_out, int out_size)
{
    (void)in_sizes; (void)n_in; (void)out_size;
    const float* x    = (const float*)d_in[0];
    const int*   mask = (const int*)d_in[1];
    const float* Wq = (const float*)d_in[2];
    const float* bq = (const float*)d_in[3];
    const float* Wk = (const float*)d_in[4];
    const float* bk = (const float*)d_in[5];
    const float* Wv = (const float*)d_in[6];
    const float* bv = (const float*)d_in[7];
    const float* Wp = (const float*)d_in[8];
    const float* bp = (const float*)d_in[9];
    float* out = (float*)d_out;

    static bool init = false;
    static __half *xh, *wh, *oh;
    if (!init) {
        cudaFuncSetAttribute(gemm_h,
            cudaFuncAttributeMaxDynamicSharedMemorySize, GEMM_SMEM2);
        cudaFuncSetAttribute(attn_h,
            cudaFuncAttributeMaxDynamicSharedMemorySize, ATT_SMEM_B);
        cudaGetSymbolAddress((void**)&xh, g_xh);
        cudaGetSymbolAddress((void**)&wh, g_Wh);
        cudaGetSymbolAddress((void**)&oh, g_Oh);
        init = true;
    }

    const int NX = Mrows * Cdim;   // 4194304
    const int NW = Cdim * Cdim;    // 1048576
    const size_t WN = (size_t)NW;

    cvt_kernel<<<NX / 2048, 256>>>(x, xh, NX);
    {
        dim3 g(NW / 2048, 4);
        cvt4_kernel<<<g, 256>>>(Wq, Wk, Wv, Wp, wh, NW);
    }

    // fused QKV projection: N = 3072 over packed Wq|Wk|Wv
    {
        dim3 g(3 * Cdim / 128, Mrows / 128);  // (24, 32)
        gemm_h<<<g, 256, GEMM_SMEM2>>>(xh, wh, bq, bk, bv, nullptr, 0);
    }

    {
        dim3 g(Tq / 128, Bsz * Hh);           // (16, 32)
        attn_h<<<g, 256, ATT_SMEM_B>>>(mask);
    }

    // output projection
    {
        dim3 g(Cdim / 128, Mrows / 128);      // (8, 32)
        gemm_h<<<g, 256, GEMM_SMEM2>>>(oh, wh + 3 * WN, bp, bp, bp, out, 1);
    }
}